// round 12
// baseline (speedup 1.0000x reference)
#include <cuda_runtime.h>
#include <cuda_bf16.h>

#define W 512
#define H 512
#define TH 16      // output rows per block (even); grid = 2048 blocks
#define EPS 1e-4f

typedef unsigned long long u64;

__device__ __forceinline__ float sqrt_approx(float x) {
    float y;
    asm("sqrt.approx.f32 %0, %1;" : "=f"(y) : "f"(x));
    return y;
}

// ---- packed f32x2 helpers (FFMA2 path, PTX-only on sm_103a) ----
__device__ __forceinline__ u64 pk2(float lo, float hi) {
    u64 r;
    asm("mov.b64 %0, {%1, %2};" : "=l"(r) : "f"(lo), "f"(hi));
    return r;
}
__device__ __forceinline__ void unpk2(u64 v, float& lo, float& hi) {
    asm("mov.b64 {%0, %1}, %2;" : "=f"(lo), "=f"(hi) : "l"(v));
}
__device__ __forceinline__ u64 fma2(u64 a, u64 b, u64 c) {
    u64 d;
    asm("fma.rn.f32x2 %0, %1, %2, %3;" : "=l"(d) : "l"(a), "l"(b), "l"(c));
    return d;
}
__device__ __forceinline__ u64 add2(u64 a, u64 b) {
    u64 d;
    asm("add.rn.f32x2 %0, %1, %2;" : "=l"(d) : "l"(a), "l"(b));
    return d;
}

#define TWO2  0x4000000040000000ull   // (2.0f, 2.0f)
#define NEG12 0xBF800000BF800000ull   // (-1.0f, -1.0f)
#define EPS2  0x3AD1B7173AD1B717ull   // (16*EPS, 16*EPS)

// Issue raw loads for one input row segment (float4 body + 2 halo scalars).
__device__ __forceinline__ void fetch_raw(const float* __restrict__ img,
                                          int y, int x0,
                                          float4& v, float& l, float& r) {
    if ((unsigned)y < (unsigned)H) {
        const float* row = img + (size_t)y * W;
        v = *(const float4*)(row + x0);
        l = (x0 > 0)     ? __ldg(row + x0 - 1) : 0.f;
        r = (x0 + 4 < W) ? __ldg(row + x0 + 4) : 0.f;
    } else {
        v = make_float4(0.f, 0.f, 0.f, 0.f);
        l = 0.f; r = 0.f;
    }
}

// Pre-reduce raw row into packed horizontal-diff d (gx part) and smooth t (gy):
//   d = (s[j]-s[j+2])          packed pairs (0,1) and (2,3)
//   t = (s[j]+2 s[j+1]+s[j+2]) packed pairs (0,1) and (2,3)
__device__ __forceinline__ void reduce_row(const float4& v, float l, float r,
                                           u64& d01, u64& d23, u64& t01, u64& t23) {
    // s0..s5 = l, v.x, v.y, v.z, v.w, r
    u64 A = pk2(l,   v.x);     // (s0,s1)
    u64 B = pk2(v.x, v.y);     // (s1,s2)
    u64 C = pk2(v.y, v.z);     // (s2,s3)
    u64 D = pk2(v.z, v.w);     // (s3,s4)
    u64 E = pk2(v.w, r);       // (s4,s5)

    d01 = fma2(C, NEG12, A);               // A - C
    d23 = fma2(E, NEG12, C);               // C - E
    t01 = fma2(B, TWO2, add2(A, C));       // A + 2B + C
    t23 = fma2(D, TWO2, add2(C, E));       // C + 2D + E
}

// gx = (dA + 2 dB + dC)/4, gy = (tA - tC)/4  ->  0.25*sqrt(u^2+v^2+16*eps)
__device__ __forceinline__ float4 magnitude(u64 dA01, u64 dA23, u64 tA01, u64 tA23,
                                            u64 dB01, u64 dB23,
                                            u64 dC01, u64 dC23, u64 tC01, u64 tC23) {
    u64 u01 = fma2(dB01, TWO2, add2(dA01, dC01));
    u64 u23 = fma2(dB23, TWO2, add2(dA23, dC23));
    u64 v01 = fma2(tC01, NEG12, tA01);
    u64 v23 = fma2(tC23, NEG12, tA23);

    u64 w01 = fma2(u01, u01, fma2(v01, v01, EPS2));
    u64 w23 = fma2(u23, u23, fma2(v23, v23, EPS2));

    float w0, w1, w2, w3;
    unpk2(w01, w0, w1);
    unpk2(w23, w2, w3);

    float4 res;
    res.x = 0.25f * sqrt_approx(w0);
    res.y = 0.25f * sqrt_approx(w1);
    res.z = 0.25f * sqrt_approx(w2);
    res.w = 0.25f * sqrt_approx(w3);
    return res;
}

__global__ __launch_bounds__(128, 8) void sobel_kernel(const float* __restrict__ in,
                                                       float* __restrict__ out) {
    const int b  = blockIdx.z;
    const int x0 = threadIdx.x * 4;          // 128 threads * 4 cols = 512 = W
    const int y0 = blockIdx.y * TH;

    const float* img = in  + (size_t)b * H * W;
    float*       o   = out + (size_t)b * H * W;

    // Reduced rolling-window rows (packed)
    u64 dA01, dA23, tA01, tA23;
    u64 dB01, dB23, tB01, tB23;
    u64 dC01, dC23, tC01, tC23;
    u64 dD01, dD23, tD01, tD23;

    // Prefetched raw rows for the NEXT iteration (software pipeline, depth 1)
    float4 p0v, p1v;
    float  p0l, p0r, p1l, p1r;

    {
        float4 vA, vB; float lA, rA, lB, rB;
        fetch_raw(img, y0 - 1, x0, vA, lA, rA);   // 12 independent LDGs
        fetch_raw(img, y0,     x0, vB, lB, rB);   // batched up front
        fetch_raw(img, y0 + 1, x0, p0v, p0l, p0r);
        fetch_raw(img, y0 + 2, x0, p1v, p1l, p1r);
        reduce_row(vA, lA, rA, dA01, dA23, tA01, tA23);
        reduce_row(vB, lB, rB, dB01, dB23, tB01, tB23);
    }

#pragma unroll
    for (int i = 0; i < TH / 2; i++) {
        const int y = y0 + 2 * i;

        // 1) Issue next iteration's loads FIRST (overlap with this iter's compute)
        float4 n0v, n1v;
        float  n0l, n0r, n1l, n1r;
        if (i < TH / 2 - 1) {                 // compile-time under full unroll
            fetch_raw(img, y + 3, x0, n0v, n0l, n0r);
            fetch_raw(img, y + 4, x0, n1v, n1l, n1r);
        }

        // 2) Consume loads issued one iteration ago
        reduce_row(p0v, p0l, p0r, dC01, dC23, tC01, tC23);   // row y+1
        reduce_row(p1v, p1l, p1r, dD01, dD23, tD01, tD23);   // row y+2

        // Two independent packed magnitude chains (ILP)
        float4 r0 = magnitude(dA01, dA23, tA01, tA23,
                              dB01, dB23,
                              dC01, dC23, tC01, tC23);        // row y
        float4 r1 = magnitude(dB01, dB23, tB01, tB23,
                              dC01, dC23,
                              dD01, dD23, tD01, tD23);        // row y+1

        __stcs((float4*)(o + (size_t)y       * W + x0), r0);
        __stcs((float4*)(o + (size_t)(y + 1) * W + x0), r1);

        // 3) Rotate window + pipeline regs (full unroll -> renaming)
        dA01 = dC01; dA23 = dC23; tA01 = tC01; tA23 = tC23;
        dB01 = dD01; dB23 = dD23; tB01 = tD01; tB23 = tD23;
        if (i < TH / 2 - 1) {
            p0v = n0v; p0l = n0l; p0r = n0r;
            p1v = n1v; p1l = n1l; p1r = n1r;
        }
    }
}

extern "C" void kernel_launch(void* const* d_in, const int* in_sizes, int n_in,
                              void* d_out, int out_size) {
    const float* x = (const float*)d_in[0];
    float* out = (float*)d_out;

    const int total = in_sizes[0];          // B * 1 * H * W
    const int B = total / (H * W);

    dim3 block(128, 1, 1);
    dim3 grid(1, H / TH, B);
    sobel_kernel<<<grid, block>>>(x, out);
}

// round 13
// speedup vs baseline: 1.0853x; 1.0853x over previous
#include <cuda_runtime.h>
#include <cuda_bf16.h>

#define W 512
#define H 512
#define TH 32      // output rows per block (even); grid = 1024 blocks
#define EPS 1e-4f

__device__ __forceinline__ float sqrt_approx(float x) {
    float y;
    asm("sqrt.approx.f32 %0, %1;" : "=f"(y) : "f"(x));
    return y;
}

// Issue raw loads for one input row segment (float4 body + 2 halo scalars).
__device__ __forceinline__ void fetch_raw(const float* __restrict__ img,
                                          int y, int x0,
                                          float4& v, float& l, float& r) {
    if ((unsigned)y < (unsigned)H) {
        const float* row = img + (size_t)y * W;
        v = *(const float4*)(row + x0);
        l = (x0 > 0)     ? __ldg(row + x0 - 1) : 0.f;
        r = (x0 + 4 < W) ? __ldg(row + x0 + 4) : 0.f;
    } else {
        v = make_float4(0.f, 0.f, 0.f, 0.f);
        l = 0.f; r = 0.f;
    }
}

// Pre-reduce raw row into horizontal-diff d[] (gx part) and smooth t[] (gy part).
__device__ __forceinline__ void reduce_row(const float4& v, float l, float r,
                                           float d[4], float t[4]) {
    float s0 = l, s1 = v.x, s2 = v.y, s3 = v.z, s4 = v.w, s5 = r;
    d[0] = s0 - s2;
    d[1] = s1 - s3;
    d[2] = s2 - s4;
    d[3] = s3 - s5;
    t[0] = fmaf(2.f, s1, s0 + s2);
    t[1] = fmaf(2.f, s2, s1 + s3);
    t[2] = fmaf(2.f, s3, s2 + s4);
    t[3] = fmaf(2.f, s4, s3 + s5);
}

// gx = (dA + 2 dB + dC)/4, gy = (tA - tC)/4  ->  0.25*sqrt(u^2+v^2+16*eps)
__device__ __forceinline__ float4 magnitude(const float dA[4], const float tA[4],
                                            const float dB[4],
                                            const float dC[4], const float tC[4]) {
    float4 res;
    float u, v;

    u = dA[0] + 2.f * dB[0] + dC[0];
    v = tA[0] - tC[0];
    res.x = 0.25f * sqrt_approx(fmaf(u, u, fmaf(v, v, 16.f * EPS)));

    u = dA[1] + 2.f * dB[1] + dC[1];
    v = tA[1] - tC[1];
    res.y = 0.25f * sqrt_approx(fmaf(u, u, fmaf(v, v, 16.f * EPS)));

    u = dA[2] + 2.f * dB[2] + dC[2];
    v = tA[2] - tC[2];
    res.z = 0.25f * sqrt_approx(fmaf(u, u, fmaf(v, v, 16.f * EPS)));

    u = dA[3] + 2.f * dB[3] + dC[3];
    v = tA[3] - tC[3];
    res.w = 0.25f * sqrt_approx(fmaf(u, u, fmaf(v, v, 16.f * EPS)));
    return res;
}

__global__ __launch_bounds__(128, 9) void sobel_kernel(const float* __restrict__ in,
                                                       float* __restrict__ out) {
    const int b  = blockIdx.z;
    const int x0 = threadIdx.x * 4;          // 128 threads * 4 cols = 512 = W
    const int y0 = blockIdx.y * TH;

    const float* img = in  + (size_t)b * H * W;
    float*       o   = out + (size_t)b * H * W;

    // Reduced rolling-window rows
    float dA[4], tA[4], dB[4], tB[4], dC[4], tC[4], dD[4], tD[4];

    // Prefetched raw rows for the NEXT iteration (software pipeline, depth 1)
    float4 p0v, p1v;
    float  p0l, p0r, p1l, p1r;

    {
        float4 vA, vB; float lA, rA, lB, rB;
        fetch_raw(img, y0 - 1, x0, vA, lA, rA);   // 12 independent LDGs
        fetch_raw(img, y0,     x0, vB, lB, rB);   // batched up front
        fetch_raw(img, y0 + 1, x0, p0v, p0l, p0r);
        fetch_raw(img, y0 + 2, x0, p1v, p1l, p1r);
        reduce_row(vA, lA, rA, dA, tA);
        reduce_row(vB, lB, rB, dB, tB);
    }

#pragma unroll
    for (int i = 0; i < TH / 2; i++) {
        const int y = y0 + 2 * i;

        // 1) Issue next iteration's loads FIRST (overlap with this iter's compute)
        float4 n0v, n1v;
        float  n0l, n0r, n1l, n1r;
        if (i < TH / 2 - 1) {                 // compile-time under full unroll
            fetch_raw(img, y + 3, x0, n0v, n0l, n0r);
            fetch_raw(img, y + 4, x0, n1v, n1l, n1r);
        }

        // 2) Consume loads issued one iteration ago
        reduce_row(p0v, p0l, p0r, dC, tC);    // row y+1
        reduce_row(p1v, p1l, p1r, dD, tD);    // row y+2

        // Two independent magnitude chains (ILP)
        float4 r0 = magnitude(dA, tA, dB, dC, tC);   // row y
        float4 r1 = magnitude(dB, tB, dC, dD, tD);   // row y+1

        __stcs((float4*)(o + (size_t)y       * W + x0), r0);
        __stcs((float4*)(o + (size_t)(y + 1) * W + x0), r1);

        // 3) Rotate window + pipeline regs (full unroll -> renaming)
#pragma unroll
        for (int j = 0; j < 4; j++) {
            dA[j] = dC[j]; tA[j] = tC[j];
            dB[j] = dD[j]; tB[j] = tD[j];
        }
        if (i < TH / 2 - 1) {
            p0v = n0v; p0l = n0l; p0r = n0r;
            p1v = n1v; p1l = n1l; p1r = n1r;
        }
    }
}

extern "C" void kernel_launch(void* const* d_in, const int* in_sizes, int n_in,
                              void* d_out, int out_size) {
    const float* x = (const float*)d_in[0];
    float* out = (float*)d_out;

    const int total = in_sizes[0];          // B * 1 * H * W
    const int B = total / (H * W);

    dim3 block(128, 1, 1);
    dim3 grid(1, H / TH, B);
    sobel_kernel<<<grid, block>>>(x, out);
}

// round 14
// speedup vs baseline: 1.1486x; 1.0583x over previous
#include <cuda_runtime.h>
#include <cuda_bf16.h>

#define W 512
#define H 512
#define TH 16      // output rows per block (even); grid = 2048 blocks
#define EPS 1e-4f

__device__ __forceinline__ float sqrt_approx(float x) {
    float y;
    asm("sqrt.approx.f32 %0, %1;" : "=f"(y) : "f"(x));
    return y;
}

// Issue raw loads for one input row segment (float4 body + 2 halo scalars).
__device__ __forceinline__ void fetch_raw(const float* __restrict__ img,
                                          int y, int x0,
                                          float4& v, float& l, float& r) {
    if ((unsigned)y < (unsigned)H) {
        const float* row = img + (size_t)y * W;
        v = *(const float4*)(row + x0);
        l = (x0 > 0)     ? __ldg(row + x0 - 1) : 0.f;
        r = (x0 + 4 < W) ? __ldg(row + x0 + 4) : 0.f;
    } else {
        v = make_float4(0.f, 0.f, 0.f, 0.f);
        l = 0.f; r = 0.f;
    }
}

// Pre-reduce raw row into horizontal-diff d[] (gx part) and smooth t[] (gy part).
__device__ __forceinline__ void reduce_row(const float4& v, float l, float r,
                                           float d[4], float t[4]) {
    float s0 = l, s1 = v.x, s2 = v.y, s3 = v.z, s4 = v.w, s5 = r;
    d[0] = s0 - s2;
    d[1] = s1 - s3;
    d[2] = s2 - s4;
    d[3] = s3 - s5;
    t[0] = fmaf(2.f, s1, s0 + s2);
    t[1] = fmaf(2.f, s2, s1 + s3);
    t[2] = fmaf(2.f, s3, s2 + s4);
    t[3] = fmaf(2.f, s4, s3 + s5);
}

// gx = (dA + 2 dB + dC)/4, gy = (tA - tC)/4  ->  0.25*sqrt(u^2+v^2+16*eps)
__device__ __forceinline__ float4 magnitude(const float dA[4], const float tA[4],
                                            const float dB[4],
                                            const float dC[4], const float tC[4]) {
    float4 res;
    float u, v;

    u = dA[0] + 2.f * dB[0] + dC[0];
    v = tA[0] - tC[0];
    res.x = 0.25f * sqrt_approx(fmaf(u, u, fmaf(v, v, 16.f * EPS)));

    u = dA[1] + 2.f * dB[1] + dC[1];
    v = tA[1] - tC[1];
    res.y = 0.25f * sqrt_approx(fmaf(u, u, fmaf(v, v, 16.f * EPS)));

    u = dA[2] + 2.f * dB[2] + dC[2];
    v = tA[2] - tC[2];
    res.z = 0.25f * sqrt_approx(fmaf(u, u, fmaf(v, v, 16.f * EPS)));

    u = dA[3] + 2.f * dB[3] + dC[3];
    v = tA[3] - tC[3];
    res.w = 0.25f * sqrt_approx(fmaf(u, u, fmaf(v, v, 16.f * EPS)));
    return res;
}

__global__ __launch_bounds__(128, 8) void sobel_kernel(const float* __restrict__ in,
                                                       float* __restrict__ out) {
    const int b  = blockIdx.z;
    const int x0 = threadIdx.x * 4;          // 128 threads * 4 cols = 512 = W
    const int y0 = blockIdx.y * TH;

    const float* img = in  + (size_t)b * H * W;
    float*       o   = out + (size_t)b * H * W;

    // Reduced rolling-window rows
    float dA[4], tA[4], dB[4], tB[4], dC[4], tC[4], dD[4], tD[4];

    // Prefetched raw rows for the NEXT iteration (software pipeline, depth 1)
    float4 p0v, p1v;
    float  p0l, p0r, p1l, p1r;

    {
        float4 vA, vB; float lA, rA, lB, rB;
        fetch_raw(img, y0 - 1, x0, vA, lA, rA);   // 12 independent LDGs
        fetch_raw(img, y0,     x0, vB, lB, rB);   // batched up front
        fetch_raw(img, y0 + 1, x0, p0v, p0l, p0r);
        fetch_raw(img, y0 + 2, x0, p1v, p1l, p1r);
        reduce_row(vA, lA, rA, dA, tA);
        reduce_row(vB, lB, rB, dB, tB);
    }

#pragma unroll
    for (int i = 0; i < TH / 2; i++) {
        const int y = y0 + 2 * i;

        // 1) Issue next iteration's loads FIRST (overlap with this iter's compute)
        float4 n0v, n1v;
        float  n0l, n0r, n1l, n1r;
        if (i < TH / 2 - 1) {                 // compile-time under full unroll
            fetch_raw(img, y + 3, x0, n0v, n0l, n0r);
            fetch_raw(img, y + 4, x0, n1v, n1l, n1r);
        }

        // 2) Consume loads issued one iteration ago
        reduce_row(p0v, p0l, p0r, dC, tC);    // row y+1
        reduce_row(p1v, p1l, p1r, dD, tD);    // row y+2

        // Two independent magnitude chains (ILP)
        float4 r0 = magnitude(dA, tA, dB, dC, tC);   // row y
        float4 r1 = magnitude(dB, tB, dC, dD, tD);   // row y+1

        __stcs((float4*)(o + (size_t)y       * W + x0), r0);
        __stcs((float4*)(o + (size_t)(y + 1) * W + x0), r1);

        // 3) Rotate window + pipeline regs (full unroll -> renaming)
#pragma unroll
        for (int j = 0; j < 4; j++) {
            dA[j] = dC[j]; tA[j] = tC[j];
            dB[j] = dD[j]; tB[j] = tD[j];
        }
        if (i < TH / 2 - 1) {
            p0v = n0v; p0l = n0l; p0r = n0r;
            p1v = n1v; p1l = n1l; p1r = n1r;
        }
    }
}

extern "C" void kernel_launch(void* const* d_in, const int* in_sizes, int n_in,
                              void* d_out, int out_size) {
    const float* x = (const float*)d_in[0];
    float* out = (float*)d_out;

    const int total = in_sizes[0];          // B * 1 * H * W
    const int B = total / (H * W);

    dim3 block(128, 1, 1);
    dim3 grid(1, H / TH, B);
    sobel_kernel<<<grid, block>>>(x, out);
}